// round 2
// baseline (speedup 1.0000x reference)
#include <cuda_runtime.h>
#include <cstdint>

#define D 128
#define EPS 1e-5f
#define MAXN 30000

// scratch (static device allocations are allowed; cudaMalloc is not)
__device__ float g_dh[MAXN * D];
__device__ float g_deg[MAXN];
__device__ float g_h[MAXN * D];

// ---------------------------------------------------------------------------
__global__ void zero_kernel(float* dh, float* deg, int n_dh, int n_deg) {
    int i = blockIdx.x * blockDim.x + threadIdx.x;
    if (i < n_dh) dh[i] = 0.f;
    if (i < n_deg) deg[i] = 0.f;
}

__global__ void deg_kernel(const int* __restrict__ tgt, float* __restrict__ deg, int E) {
    int i = blockIdx.x * blockDim.x + threadIdx.x;
    if (i < E) atomicAdd(&deg[tgt[i]], 1.0f);
}

// ---------------------------------------------------------------------------
// Fused 3-layer edge MLP over a tile of 128 edges.
// Stage1: X[128x384] @ W1[384x128] (+b1, relu)
// Stage2: T @ W2[128x128]          (+b2, relu)
// Stage3: T @ W3[128x128]          (+b3) -> atomic scatter-add into dh[tgt]
// Thread block: 256 threads as 16x16; each thread owns an 8x8 C sub-tile.
__global__ void __launch_bounds__(256, 2) edge_mlp_kernel(
    const float* __restrict__ hE, const float* __restrict__ hV,
    const int* __restrict__ src, const int* __restrict__ tgt,
    const float* __restrict__ w1, const float* __restrict__ b1,
    const float* __restrict__ w2, const float* __restrict__ b2,
    const float* __restrict__ w3, const float* __restrict__ b3,
    float* __restrict__ dh, int E)
{
    extern __shared__ float smem[];
    float* Ts = smem;                 // 128*129
    float* As = Ts + 128 * 129;       // 128*33
    float* Bs = As + 128 * 33;        // 32*128
    int* s_src = (int*)(Bs + 32 * 128);
    int* s_tgt = s_src + 128;

    const int tid = threadIdx.x;
    const int tx = tid & 15, ty = tid >> 4;
    const int e0 = blockIdx.x * 128;

    for (int i = tid; i < 128; i += 256) {
        int e = e0 + i;
        s_src[i] = (e < E) ? src[e] : 0;
        s_tgt[i] = (e < E) ? tgt[e] : 0;
    }
    __syncthreads();

    float acc[8][8];
#pragma unroll
    for (int i = 0; i < 8; i++)
#pragma unroll
        for (int j = 0; j < 8; j++) acc[i][j] = 0.f;

    // ---- stage 1 ----
    for (int kc = 0; kc < 3 * D; kc += 32) {
        // gather X chunk (As[row][kk]): 32 consecutive cols per edge row
        for (int i = tid; i < 128 * 32; i += 256) {
            int row = i >> 5, kk = i & 31;
            int col = kc + kk;
            int e = e0 + row;
            float v = 0.f;
            if (e < E) {
                if (col < D)            v = hE[(size_t)e * D + col];
                else if (col < 2 * D)   v = hV[(size_t)s_src[row] * D + (col - D)];
                else                    v = hV[(size_t)s_tgt[row] * D + (col - 2 * D)];
            }
            As[row * 33 + kk] = v;
        }
        for (int i = tid; i < 32 * 128; i += 256) {
            int kk = i >> 7, j = i & 127;
            Bs[kk * 128 + j] = w1[(size_t)(kc + kk) * D + j];
        }
        __syncthreads();
#pragma unroll 4
        for (int kk = 0; kk < 32; kk++) {
            float a[8], b[8];
#pragma unroll
            for (int i = 0; i < 8; i++) a[i] = As[(ty * 8 + i) * 33 + kk];
            float4 bl = *(const float4*)&Bs[kk * 128 + tx * 8];
            float4 bh = *(const float4*)&Bs[kk * 128 + tx * 8 + 4];
            b[0] = bl.x; b[1] = bl.y; b[2] = bl.z; b[3] = bl.w;
            b[4] = bh.x; b[5] = bh.y; b[6] = bh.z; b[7] = bh.w;
#pragma unroll
            for (int i = 0; i < 8; i++)
#pragma unroll
                for (int j = 0; j < 8; j++) acc[i][j] = fmaf(a[i], b[j], acc[i][j]);
        }
        __syncthreads();
    }
    // bias + relu -> Ts
#pragma unroll
    for (int i = 0; i < 8; i++)
#pragma unroll
        for (int j = 0; j < 8; j++) {
            float v = acc[i][j] + __ldg(&b1[tx * 8 + j]);
            Ts[(ty * 8 + i) * 129 + tx * 8 + j] = fmaxf(v, 0.f);
            acc[i][j] = 0.f;
        }
    __syncthreads();

    // ---- stage 2 ----
    for (int kc = 0; kc < D; kc += 32) {
        for (int i = tid; i < 32 * 128; i += 256) {
            int kk = i >> 7, j = i & 127;
            Bs[kk * 128 + j] = w2[(size_t)(kc + kk) * D + j];
        }
        __syncthreads();
#pragma unroll 4
        for (int kk = 0; kk < 32; kk++) {
            float a[8], b[8];
#pragma unroll
            for (int i = 0; i < 8; i++) a[i] = Ts[(ty * 8 + i) * 129 + kc + kk];
            float4 bl = *(const float4*)&Bs[kk * 128 + tx * 8];
            float4 bh = *(const float4*)&Bs[kk * 128 + tx * 8 + 4];
            b[0] = bl.x; b[1] = bl.y; b[2] = bl.z; b[3] = bl.w;
            b[4] = bh.x; b[5] = bh.y; b[6] = bh.z; b[7] = bh.w;
#pragma unroll
            for (int i = 0; i < 8; i++)
#pragma unroll
                for (int j = 0; j < 8; j++) acc[i][j] = fmaf(a[i], b[j], acc[i][j]);
        }
        __syncthreads();
    }
#pragma unroll
    for (int i = 0; i < 8; i++)
#pragma unroll
        for (int j = 0; j < 8; j++) {
            float v = acc[i][j] + __ldg(&b2[tx * 8 + j]);
            acc[i][j] = fmaxf(v, 0.f);   // stash relu'd stage-2 in regs first
        }
    __syncthreads();
#pragma unroll
    for (int i = 0; i < 8; i++)
#pragma unroll
        for (int j = 0; j < 8; j++) {
            Ts[(ty * 8 + i) * 129 + tx * 8 + j] = acc[i][j];
            acc[i][j] = 0.f;
        }
    __syncthreads();

    // ---- stage 3 ----
    for (int kc = 0; kc < D; kc += 32) {
        for (int i = tid; i < 32 * 128; i += 256) {
            int kk = i >> 7, j = i & 127;
            Bs[kk * 128 + j] = w3[(size_t)(kc + kk) * D + j];
        }
        __syncthreads();
#pragma unroll 4
        for (int kk = 0; kk < 32; kk++) {
            float a[8], b[8];
#pragma unroll
            for (int i = 0; i < 8; i++) a[i] = Ts[(ty * 8 + i) * 129 + kc + kk];
            float4 bl = *(const float4*)&Bs[kk * 128 + tx * 8];
            float4 bh = *(const float4*)&Bs[kk * 128 + tx * 8 + 4];
            b[0] = bl.x; b[1] = bl.y; b[2] = bl.z; b[3] = bl.w;
            b[4] = bh.x; b[5] = bh.y; b[6] = bh.z; b[7] = bh.w;
#pragma unroll
            for (int i = 0; i < 8; i++)
#pragma unroll
                for (int j = 0; j < 8; j++) acc[i][j] = fmaf(a[i], b[j], acc[i][j]);
        }
        __syncthreads();
    }

    // bias + atomic scatter-add into dh[tgt]
#pragma unroll
    for (int i = 0; i < 8; i++) {
        int row = ty * 8 + i;
        int e = e0 + row;
        if (e >= E) continue;
        int t = s_tgt[row];
        float* drow = &dh[(size_t)t * D + tx * 8];
#pragma unroll
        for (int j = 0; j < 8; j++) {
            atomicAdd(&drow[j], acc[i][j] + __ldg(&b3[tx * 8 + j]));
        }
    }
}

// ---------------------------------------------------------------------------
// h = LayerNorm(h_V + dh/deg) ; one warp per node row
__global__ void ln0_kernel(const float* __restrict__ hV, const float* __restrict__ dh,
                           const float* __restrict__ deg,
                           const float* __restrict__ w, const float* __restrict__ b,
                           float* __restrict__ h, int N)
{
    int row = (blockIdx.x * blockDim.x + threadIdx.x) >> 5;
    int lane = threadIdx.x & 31;
    if (row >= N) return;
    float inv_deg = 1.0f / fmaxf(deg[row], 1.0f);
    float v[4];
    float s = 0.f;
#pragma unroll
    for (int k = 0; k < 4; k++) {
        int c = lane + 32 * k;
        v[k] = hV[(size_t)row * D + c] + dh[(size_t)row * D + c] * inv_deg;
        s += v[k];
    }
#pragma unroll
    for (int o = 16; o > 0; o >>= 1) s += __shfl_xor_sync(0xffffffffu, s, o);
    float mean = s * (1.0f / 128.0f);
    float sq = 0.f;
#pragma unroll
    for (int k = 0; k < 4; k++) { float d = v[k] - mean; sq += d * d; }
#pragma unroll
    for (int o = 16; o > 0; o >>= 1) sq += __shfl_xor_sync(0xffffffffu, sq, o);
    float rstd = rsqrtf(sq * (1.0f / 128.0f) + EPS);
#pragma unroll
    for (int k = 0; k < 4; k++) {
        int c = lane + 32 * k;
        h[(size_t)row * D + c] = (v[k] - mean) * rstd * w[c] + b[c];
    }
}

// ---------------------------------------------------------------------------
// out = LayerNorm(h + relu(h@W1+b1)@W2 + b2); W1:[128,512], W2:[512,128]
// split 512 into 4 chunks of 128: out_pre = h + b2 + sum_c relu(h@W1[:,c])@W2[c,:]
__global__ void __launch_bounds__(256, 1) ffn_kernel(
    const float* __restrict__ h,
    const float* __restrict__ w1, const float* __restrict__ b1,
    const float* __restrict__ w2, const float* __restrict__ b2,
    const float* __restrict__ lnw, const float* __restrict__ lnb,
    float* __restrict__ out, int N)
{
    extern __shared__ float smem[];
    float* Hs = smem;                 // 128*129
    float* Us = Hs + 128 * 129;       // 128*129
    float* Bs = Us + 128 * 129;       // 32*128

    const int tid = threadIdx.x;
    const int tx = tid & 15, ty = tid >> 4;
    const int r0 = blockIdx.x * 128;

    for (int i = tid; i < 128 * 128; i += 256) {
        int r = i >> 7, c = i & 127;
        int gr = r0 + r;
        Hs[r * 129 + c] = (gr < N) ? h[(size_t)gr * D + c] : 0.f;
    }
    __syncthreads();

    float acc2[8][8];
#pragma unroll
    for (int i = 0; i < 8; i++)
#pragma unroll
        for (int j = 0; j < 8; j++) acc2[i][j] = 0.f;

    for (int c4 = 0; c4 < 4; c4++) {
        float acc1[8][8];
#pragma unroll
        for (int i = 0; i < 8; i++)
#pragma unroll
            for (int j = 0; j < 8; j++) acc1[i][j] = 0.f;

        // GEMM1: Hs @ W1[:, c4*128 : +128]
        for (int kc = 0; kc < D; kc += 32) {
            for (int i = tid; i < 32 * 128; i += 256) {
                int kk = i >> 7, j = i & 127;
                Bs[kk * 128 + j] = w1[(size_t)(kc + kk) * (4 * D) + c4 * 128 + j];
            }
            __syncthreads();
#pragma unroll 4
            for (int kk = 0; kk < 32; kk++) {
                float a[8], b[8];
#pragma unroll
                for (int i = 0; i < 8; i++) a[i] = Hs[(ty * 8 + i) * 129 + kc + kk];
                float4 bl = *(const float4*)&Bs[kk * 128 + tx * 8];
                float4 bh = *(const float4*)&Bs[kk * 128 + tx * 8 + 4];
                b[0] = bl.x; b[1] = bl.y; b[2] = bl.z; b[3] = bl.w;
                b[4] = bh.x; b[5] = bh.y; b[6] = bh.z; b[7] = bh.w;
#pragma unroll
                for (int i = 0; i < 8; i++)
#pragma unroll
                    for (int j = 0; j < 8; j++) acc1[i][j] = fmaf(a[i], b[j], acc1[i][j]);
            }
            __syncthreads();
        }
        // relu + bias -> Us
#pragma unroll
        for (int i = 0; i < 8; i++)
#pragma unroll
            for (int j = 0; j < 8; j++) {
                float v = acc1[i][j] + __ldg(&b1[c4 * 128 + tx * 8 + j]);
                Us[(ty * 8 + i) * 129 + tx * 8 + j] = fmaxf(v, 0.f);
            }
        __syncthreads();

        // GEMM2: Us @ W2[c4*128 : +128, :], accumulate into acc2
        for (int kc = 0; kc < D; kc += 32) {
            for (int i = tid; i < 32 * 128; i += 256) {
                int kk = i >> 7, j = i & 127;
                Bs[kk * 128 + j] = w2[(size_t)(c4 * 128 + kc + kk) * D + j];
            }
            __syncthreads();
#pragma unroll 4
            for (int kk = 0; kk < 32; kk++) {
                float a[8], b[8];
#pragma unroll
                for (int i = 0; i < 8; i++) a[i] = Us[(ty * 8 + i) * 129 + kc + kk];
                float4 bl = *(const float4*)&Bs[kk * 128 + tx * 8];
                float4 bh = *(const float4*)&Bs[kk * 128 + tx * 8 + 4];
                b[0] = bl.x; b[1] = bl.y; b[2] = bl.z; b[3] = bl.w;
                b[4] = bh.x; b[5] = bh.y; b[6] = bh.z; b[7] = bh.w;
#pragma unroll
                for (int i = 0; i < 8; i++)
#pragma unroll
                    for (int j = 0; j < 8; j++) acc2[i][j] = fmaf(a[i], b[j], acc2[i][j]);
            }
            __syncthreads();
        }
    }

    // pre-LN values -> Us
#pragma unroll
    for (int i = 0; i < 8; i++)
#pragma unroll
        for (int j = 0; j < 8; j++) {
            int r = ty * 8 + i, c = tx * 8 + j;
            Us[r * 129 + c] = Hs[r * 129 + c] + acc2[i][j] + __ldg(&b2[c]);
        }
    __syncthreads();

    // LayerNorm per row (8 warps, 16 rows each)
    int warp = tid >> 5, lane = tid & 31;
    for (int r = warp; r < 128; r += 8) {
        int gr = r0 + r;
        if (gr >= N) continue;
        float v[4], s = 0.f;
#pragma unroll
        for (int k = 0; k < 4; k++) { v[k] = Us[r * 129 + lane + 32 * k]; s += v[k]; }
#pragma unroll
        for (int o = 16; o > 0; o >>= 1) s += __shfl_xor_sync(0xffffffffu, s, o);
        float mean = s * (1.0f / 128.0f);
        float sq = 0.f;
#pragma unroll
        for (int k = 0; k < 4; k++) { float d = v[k] - mean; sq += d * d; }
#pragma unroll
        for (int o = 16; o > 0; o >>= 1) sq += __shfl_xor_sync(0xffffffffu, sq, o);
        float rstd = rsqrtf(sq * (1.0f / 128.0f) + EPS);
#pragma unroll
        for (int k = 0; k < 4; k++) {
            int c = lane + 32 * k;
            out[(size_t)gr * D + c] = (v[k] - mean) * rstd * lnw[c] + lnb[c];
        }
    }
}

// ---------------------------------------------------------------------------
extern "C" void kernel_launch(void* const* d_in, const int* in_sizes, int n_in,
                              void* d_out, int out_size)
{
    const float* hV  = (const float*)d_in[0];
    const float* hE  = (const float*)d_in[1];
    const int*   src = (const int*)d_in[2];
    const int*   tgt = (const int*)d_in[3];
    const float* w1  = (const float*)d_in[4];
    const float* b1  = (const float*)d_in[5];
    const float* w2  = (const float*)d_in[6];
    const float* b2  = (const float*)d_in[7];
    const float* w3  = (const float*)d_in[8];
    const float* b3  = (const float*)d_in[9];
    const float* ln0w = (const float*)d_in[10];
    const float* ln0b = (const float*)d_in[11];
    const float* ln1w = (const float*)d_in[12];
    const float* ln1b = (const float*)d_in[13];
    const float* fw1 = (const float*)d_in[14];
    const float* fb1 = (const float*)d_in[15];
    const float* fw2 = (const float*)d_in[16];
    const float* fb2 = (const float*)d_in[17];
    float* out = (float*)d_out;

    const int N = in_sizes[0] / D;
    const int E = in_sizes[1] / D;

    void *p_dh, *p_deg, *p_h;
    cudaGetSymbolAddress(&p_dh, g_dh);
    cudaGetSymbolAddress(&p_deg, g_deg);
    cudaGetSymbolAddress(&p_h, g_h);
    float* dh  = (float*)p_dh;
    float* deg = (float*)p_deg;
    float* h   = (float*)p_h;

    // opt-in to large dynamic smem (idempotent, non-stream API)
    const int edge_smem = (128 * 129 + 128 * 33 + 32 * 128) * 4 + 256 * 4;
    const int ffn_smem  = (128 * 129 * 2 + 32 * 128) * 4;
    cudaFuncSetAttribute(edge_mlp_kernel, cudaFuncAttributeMaxDynamicSharedMemorySize, edge_smem);
    cudaFuncSetAttribute(ffn_kernel, cudaFuncAttributeMaxDynamicSharedMemorySize, ffn_smem);

    // 1. zero scratch
    {
        int n_dh = N * D;
        int grid = (n_dh + 255) / 256;
        zero_kernel<<<grid, 256>>>(dh, deg, n_dh, N);
    }
    // 2. degrees
    deg_kernel<<<(E + 255) / 256, 256>>>(tgt, deg, E);
    // 3. fused edge MLP + scatter-add
    edge_mlp_kernel<<<(E + 127) / 128, 256, edge_smem>>>(
        hE, hV, src, tgt, w1, b1, w2, b2, w3, b3, dh, E);
    // 4. residual + LN0 -> h
    ln0_kernel<<<(N * 32 + 255) / 256, 256>>>(hV, dh, deg, ln0w, ln0b, h, N);
    // 5. FFN + residual + LN1 -> out
    ffn_kernel<<<(N + 127) / 128, 256, ffn_smem>>>(
        h, fw1, fb1, fw2, fb2, ln1w, ln1b, out, N);
}

// round 4
// speedup vs baseline: 1.8632x; 1.8632x over previous
#include <cuda_runtime.h>
#include <mma.h>
#include <cstdint>

using namespace nvcuda;

#define EPS 1e-5f
#define NMAX 30720
#define LDT 132   // 128x128 f32 tile stride (pad 4)
#define LDA 40    // 128x32 A-chunk stride (pad 8)
#define LDB 136   // 32x128 B-chunk stride (pad 8)

// ---------------- static device scratch ----------------
__device__ float g_dh[(size_t)NMAX * 128];
__device__ float g_deg[NMAX];
__device__ float g_h[(size_t)NMAX * 128];

// ---------------- WMMA helpers ----------------
using FragA = wmma::fragment<wmma::matrix_a, 16, 16, 8, wmma::precision::tf32, wmma::row_major>;
using FragB = wmma::fragment<wmma::matrix_b, 16, 16, 8, wmma::precision::tf32, wmma::row_major>;
using FragC = wmma::fragment<wmma::accumulator, 16, 16, 8, float>;

// One K=32 chunk: acc[2][4] covers warp tile 32(M) x 64(N).
// A: base pointer at column 0 of this chunk, stride lda. B: 32xLDB smem chunk.
__device__ __forceinline__ void mma_chunk32(FragC acc[2][4], const float* A, int lda,
                                            const float* B, int wm, int wn) {
#pragma unroll
    for (int kk = 0; kk < 32; kk += 8) {
        FragA a[2];
#pragma unroll
        for (int mi = 0; mi < 2; mi++) {
            wmma::load_matrix_sync(a[mi], A + (size_t)(wm * 32 + mi * 16) * lda + kk, lda);
#pragma unroll
            for (int t = 0; t < a[mi].num_elements; t++)
                a[mi].x[t] = wmma::__float_to_tf32(a[mi].x[t]);
        }
#pragma unroll
        for (int nj = 0; nj < 4; nj++) {
            FragB b;
            wmma::load_matrix_sync(b, B + kk * LDB + wn * 64 + nj * 16, LDB);
#pragma unroll
            for (int t = 0; t < b.num_elements; t++)
                b.x[t] = wmma::__float_to_tf32(b.x[t]);
#pragma unroll
            for (int mi = 0; mi < 2; mi++)
                wmma::mma_sync(acc[mi][nj], a[mi], b, acc[mi][nj]);
        }
    }
}

__device__ __forceinline__ void zero_acc(FragC acc[2][4]) {
#pragma unroll
    for (int mi = 0; mi < 2; mi++)
#pragma unroll
        for (int nj = 0; nj < 4; nj++) wmma::fill_fragment(acc[mi][nj], 0.0f);
}

__device__ __forceinline__ void store_acc(FragC acc[2][4], float* Ts, int wm, int wn) {
#pragma unroll
    for (int mi = 0; mi < 2; mi++)
#pragma unroll
        for (int nj = 0; nj < 4; nj++)
            wmma::store_matrix_sync(&Ts[(size_t)(wm * 32 + mi * 16) * LDT + wn * 64 + nj * 16],
                                    acc[mi][nj], LDT, wmma::mem_row_major);
}

// ---------------- small kernels ----------------
__global__ void zero_kernel(float* dh, float* deg, int n_dh, int n_deg) {
    int i = blockIdx.x * blockDim.x + threadIdx.x;
    if (i < n_dh) dh[i] = 0.f;
    if (i < n_deg) deg[i] = 0.f;
}

__global__ void deg_kernel(const int* __restrict__ tgt, float* __restrict__ deg, int E) {
    int i = blockIdx.x * blockDim.x + threadIdx.x;
    if (i < E) atomicAdd(&deg[tgt[i]], 1.0f);
}

// h = LayerNorm(h_V + dh/deg); one warp per row
__global__ void ln0_kernel(const float* __restrict__ hV, const float* __restrict__ dh,
                           const float* __restrict__ deg,
                           const float* __restrict__ w, const float* __restrict__ b,
                           float* __restrict__ h, int N) {
    int row = (blockIdx.x * blockDim.x + threadIdx.x) >> 5;
    int lane = threadIdx.x & 31;
    if (row >= N) return;
    float inv_deg = 1.0f / fmaxf(deg[row], 1.0f);
    float v[4];
    float s = 0.f;
#pragma unroll
    for (int k = 0; k < 4; k++) {
        int c = lane + 32 * k;
        v[k] = hV[(size_t)row * 128 + c] + dh[(size_t)row * 128 + c] * inv_deg;
        s += v[k];
    }
#pragma unroll
    for (int o = 16; o > 0; o >>= 1) s += __shfl_xor_sync(0xffffffffu, s, o);
    float mean = s * (1.0f / 128.0f);
    float sq = 0.f;
#pragma unroll
    for (int k = 0; k < 4; k++) { float d = v[k] - mean; sq += d * d; }
#pragma unroll
    for (int o = 16; o > 0; o >>= 1) sq += __shfl_xor_sync(0xffffffffu, sq, o);
    float rstd = rsqrtf(sq * (1.0f / 128.0f) + EPS);
#pragma unroll
    for (int k = 0; k < 4; k++) {
        int c = lane + 32 * k;
        h[(size_t)row * 128 + c] = (v[k] - mean) * rstd * w[c] + b[c];
    }
}

// ---------------- edge MLP (WMMA tf32) ----------------
// smem: Ts[128*LDT] | As[128*LDA] | Bs[32*LDB] | s_src[128] | s_tgt[128]
#define EDGE_SMEM ((128 * LDT + 128 * LDA + 32 * LDB) * 4 + 256 * 4)

__global__ void __launch_bounds__(256, 2) edge_mma_kernel(
    const float* __restrict__ hE, const float* __restrict__ hV,
    const int* __restrict__ src, const int* __restrict__ tgt,
    const float* __restrict__ w1, const float* __restrict__ b1,
    const float* __restrict__ w2, const float* __restrict__ b2,
    const float* __restrict__ w3, const float* __restrict__ b3,
    float* __restrict__ dh, int E)
{
    extern __shared__ float sm[];
    float* Ts = sm;
    float* As = Ts + 128 * LDT;
    float* Bs = As + 128 * LDA;
    int* s_src = (int*)(Bs + 32 * LDB);
    int* s_tgt = s_src + 128;

    const int tid = threadIdx.x;
    const int wid = tid >> 5;
    const int wm = wid & 3;   // M strip: rows 32*wm
    const int wn = wid >> 2;  // N strip: cols 64*wn
    const int e0 = blockIdx.x * 128;

    if (tid < 128) {
        int e = e0 + tid;
        s_src[tid] = (e < E) ? src[e] : 0;
        s_tgt[tid] = (e < E) ? tgt[e] : 0;
    }
    __syncthreads();

    FragC acc[2][4];
    zero_acc(acc);

    // ---- stage 1: K = 384 in 12 chunks of 32 ----
    for (int kc = 0; kc < 12; kc++) {
        const int jsel = (kc * 32) >> 7;       // which source third
        const int c0 = (kc * 32) & 127;        // col within source
        // gather A chunk (128x32) as float4
        for (int idx = tid; idx < 1024; idx += 256) {
            int r = idx >> 3, q = idx & 7;
            const float* rowp;
            if (jsel == 0) {
                int e = e0 + r; if (e >= E) e = E - 1;
                rowp = hE + (size_t)e * 128;
            } else if (jsel == 1) rowp = hV + (size_t)s_src[r] * 128;
            else                  rowp = hV + (size_t)s_tgt[r] * 128;
            *(float4*)&As[r * LDA + q * 4] = *(const float4*)&rowp[c0 + q * 4];
        }
        // stage B chunk (32x128) from w1
        for (int idx = tid; idx < 1024; idx += 256) {
            int kk = idx >> 5, q = idx & 31;
            *(float4*)&Bs[kk * LDB + q * 4] =
                *(const float4*)&w1[(size_t)(kc * 32 + kk) * 128 + q * 4];
        }
        __syncthreads();
        mma_chunk32(acc, As, LDA, Bs, wm, wn);
        __syncthreads();
    }
    // bias + relu -> Ts
    store_acc(acc, Ts, wm, wn);
    __syncthreads();
    for (int idx = tid; idx < 4096; idx += 256) {
        int r = idx >> 5, q = idx & 31, c = q * 4;
        float4 v = *(float4*)&Ts[r * LDT + c];
        v.x = fmaxf(v.x + __ldg(&b1[c + 0]), 0.f);
        v.y = fmaxf(v.y + __ldg(&b1[c + 1]), 0.f);
        v.z = fmaxf(v.z + __ldg(&b1[c + 2]), 0.f);
        v.w = fmaxf(v.w + __ldg(&b1[c + 3]), 0.f);
        *(float4*)&Ts[r * LDT + c] = v;
    }
    __syncthreads();

    // ---- stage 2: K = 128 ----
    zero_acc(acc);
    for (int kc = 0; kc < 4; kc++) {
        for (int idx = tid; idx < 1024; idx += 256) {
            int kk = idx >> 5, q = idx & 31;
            *(float4*)&Bs[kk * LDB + q * 4] =
                *(const float4*)&w2[(size_t)(kc * 32 + kk) * 128 + q * 4];
        }
        __syncthreads();
        mma_chunk32(acc, Ts + kc * 32, LDT, Bs, wm, wn);
        __syncthreads();
    }
    store_acc(acc, Ts, wm, wn);
    __syncthreads();
    for (int idx = tid; idx < 4096; idx += 256) {
        int r = idx >> 5, q = idx & 31, c = q * 4;
        float4 v = *(float4*)&Ts[r * LDT + c];
        v.x = fmaxf(v.x + __ldg(&b2[c + 0]), 0.f);
        v.y = fmaxf(v.y + __ldg(&b2[c + 1]), 0.f);
        v.z = fmaxf(v.z + __ldg(&b2[c + 2]), 0.f);
        v.w = fmaxf(v.w + __ldg(&b2[c + 3]), 0.f);
        *(float4*)&Ts[r * LDT + c] = v;
    }
    __syncthreads();

    // ---- stage 3: K = 128 ----
    zero_acc(acc);
    for (int kc = 0; kc < 4; kc++) {
        for (int idx = tid; idx < 1024; idx += 256) {
            int kk = idx >> 5, q = idx & 31;
            *(float4*)&Bs[kk * LDB + q * 4] =
                *(const float4*)&w3[(size_t)(kc * 32 + kk) * 128 + q * 4];
        }
        __syncthreads();
        mma_chunk32(acc, Ts + kc * 32, LDT, Bs, wm, wn);
        __syncthreads();
    }
    store_acc(acc, Ts, wm, wn);
    __syncthreads();

    // bias + coalesced atomic scatter into dh[tgt]
    for (int idx = tid; idx < 16384; idx += 256) {
        int r = idx >> 7, c = idx & 127;
        if (e0 + r < E)
            atomicAdd(&dh[(size_t)s_tgt[r] * 128 + c], Ts[r * LDT + c] + __ldg(&b3[c]));
    }
}

// ---------------- FFN + LN1 (WMMA tf32) ----------------
// smem: Hs[128*LDT] | Us[128*LDT] | Bs[32*LDB]
#define FFN_SMEM ((128 * LDT * 2 + 32 * LDB) * 4)

__global__ void __launch_bounds__(256) ffn_mma_kernel(
    const float* __restrict__ h,
    const float* __restrict__ fw1, const float* __restrict__ fb1,
    const float* __restrict__ fw2, const float* __restrict__ fb2,
    const float* __restrict__ lnw, const float* __restrict__ lnb,
    float* __restrict__ out, int N)
{
    extern __shared__ float sm[];
    float* Hs = sm;
    float* Us = Hs + 128 * LDT;
    float* Bs = Us + 128 * LDT;

    const int tid = threadIdx.x;
    const int wid = tid >> 5, lane = tid & 31;
    const int wm = wid & 3, wn = wid >> 2;
    const int r0 = blockIdx.x * 128;

    // load Hs (f32 h tile; zeros out of range)
    for (int idx = tid; idx < 4096; idx += 256) {
        int r = idx >> 5, q = idx & 31;
        int gr = r0 + r;
        float4 v = make_float4(0.f, 0.f, 0.f, 0.f);
        if (gr < N) v = *(const float4*)&h[(size_t)gr * 128 + q * 4];
        *(float4*)&Hs[r * LDT + q * 4] = v;
    }
    __syncthreads();

    FragC acc2[2][4];
    zero_acc(acc2);

    for (int c4 = 0; c4 < 4; c4++) {
        FragC acc1[2][4];
        zero_acc(acc1);
        // GEMM1: Hs @ fw1[:, c4*128 : +128]
        for (int kc = 0; kc < 4; kc++) {
            for (int idx = tid; idx < 1024; idx += 256) {
                int kk = idx >> 5, q = idx & 31;
                *(float4*)&Bs[kk * LDB + q * 4] =
                    *(const float4*)&fw1[(size_t)(kc * 32 + kk) * 512 + c4 * 128 + q * 4];
            }
            __syncthreads();
            mma_chunk32(acc1, Hs + kc * 32, LDT, Bs, wm, wn);
            __syncthreads();
        }
        store_acc(acc1, Us, wm, wn);
        __syncthreads();
        for (int idx = tid; idx < 4096; idx += 256) {
            int r = idx >> 5, q = idx & 31, c = q * 4;
            float4 v = *(float4*)&Us[r * LDT + c];
            v.x = fmaxf(v.x + __ldg(&fb1[c4 * 128 + c + 0]), 0.f);
            v.y = fmaxf(v.y + __ldg(&fb1[c4 * 128 + c + 1]), 0.f);
            v.z = fmaxf(v.z + __ldg(&fb1[c4 * 128 + c + 2]), 0.f);
            v.w = fmaxf(v.w + __ldg(&fb1[c4 * 128 + c + 3]), 0.f);
            *(float4*)&Us[r * LDT + c] = v;
        }
        __syncthreads();
        // GEMM2: Us @ fw2[c4*128 : +128, :], accumulate acc2
        for (int kc = 0; kc < 4; kc++) {
            for (int idx = tid; idx < 1024; idx += 256) {
                int kk = idx >> 5, q = idx & 31;
                *(float4*)&Bs[kk * LDB + q * 4] =
                    *(const float4*)&fw2[(size_t)(c4 * 128 + kc * 32 + kk) * 128 + q * 4];
            }
            __syncthreads();
            mma_chunk32(acc2, Us + kc * 32, LDT, Bs, wm, wn);
            __syncthreads();
        }
    }

    // epilogue: pre-LN = Hs + acc2 + fb2; LayerNorm per row
    store_acc(acc2, Us, wm, wn);
    __syncthreads();
#pragma unroll
    for (int i = 0; i < 16; i++) {
        int r = wid * 16 + i;
        int gr = r0 + r;
        if (gr >= N) continue;
        float v[4], s = 0.f;
#pragma unroll
        for (int k = 0; k < 4; k++) {
            int c = lane + 32 * k;
            v[k] = Hs[r * LDT + c] + Us[r * LDT + c] + __ldg(&fb2[c]);
            s += v[k];
        }
#pragma unroll
        for (int o = 16; o > 0; o >>= 1) s += __shfl_xor_sync(0xffffffffu, s, o);
        float mean = s * (1.0f / 128.0f);
        float sq = 0.f;
#pragma unroll
        for (int k = 0; k < 4; k++) { float d = v[k] - mean; sq += d * d; }
#pragma unroll
        for (int o = 16; o > 0; o >>= 1) sq += __shfl_xor_sync(0xffffffffu, sq, o);
        float rstd = rsqrtf(sq * (1.0f / 128.0f) + EPS);
#pragma unroll
        for (int k = 0; k < 4; k++) {
            int c = lane + 32 * k;
            out[(size_t)gr * 128 + c] = (v[k] - mean) * rstd * __ldg(&lnw[c]) + __ldg(&lnb[c]);
        }
    }
}

// ---------------------------------------------------------------------------
extern "C" void kernel_launch(void* const* d_in, const int* in_sizes, int n_in,
                              void* d_out, int out_size)
{
    const float* hV  = (const float*)d_in[0];
    const float* hE  = (const float*)d_in[1];
    const int*   src = (const int*)d_in[2];
    const int*   tgt = (const int*)d_in[3];
    const float* w1  = (const float*)d_in[4];
    const float* b1  = (const float*)d_in[5];
    const float* w2  = (const float*)d_in[6];
    const float* b2  = (const float*)d_in[7];
    const float* w3  = (const float*)d_in[8];
    const float* b3  = (const float*)d_in[9];
    const float* ln0w = (const float*)d_in[10];
    const float* ln0b = (const float*)d_in[11];
    const float* ln1w = (const float*)d_in[12];
    const float* ln1b = (const float*)d_in[13];
    const float* fw1 = (const float*)d_in[14];
    const float* fb1 = (const float*)d_in[15];
    const float* fw2 = (const float*)d_in[16];
    const float* fb2 = (const float*)d_in[17];
    float* out = (float*)d_out;

    const int N = in_sizes[0] / 128;
    const int E = in_sizes[1] / 128;

    void *p_dh, *p_deg, *p_h;
    cudaGetSymbolAddress(&p_dh, g_dh);
    cudaGetSymbolAddress(&p_deg, g_deg);
    cudaGetSymbolAddress(&p_h, g_h);
    float* dh  = (float*)p_dh;
    float* deg = (float*)p_deg;
    float* h   = (float*)p_h;

    cudaFuncSetAttribute(edge_mma_kernel, cudaFuncAttributeMaxDynamicSharedMemorySize, EDGE_SMEM);
    cudaFuncSetAttribute(ffn_mma_kernel, cudaFuncAttributeMaxDynamicSharedMemorySize, FFN_SMEM);

    zero_kernel<<<(N * 128 + 255) / 256, 256>>>(dh, deg, N * 128, N);
    deg_kernel<<<(E + 255) / 256, 256>>>(tgt, deg, E);
    edge_mma_kernel<<<(E + 127) / 128, 256, EDGE_SMEM>>>(
        hE, hV, src, tgt, w1, b1, w2, b2, w3, b3, dh, E);
    ln0_kernel<<<(N * 32 + 255) / 256, 256>>>(hV, dh, deg, ln0w, ln0b, h, N);
    ffn_mma_kernel<<<(N + 127) / 128, 256, FFN_SMEM>>>(
        h, fw1, fb1, fw2, fb2, ln1w, ln1b, out, N);
}